// round 16
// baseline (speedup 1.0000x reference)
#include <cuda_runtime.h>
#include <cuda_fp16.h>
#include <cuda_fp8.h>
#include <cstdint>
#include <cstddef>

#define B_    2
#define L_    192
#define H_    512
#define NH_   8
#define ML_   (B_*L_)     // 384 rows (b,l) flattened
#define TROWS_ 383        // distinct position diffs: [-191, 191]
#define SCP_  196         // padded score row
#define GP_   520         // padded half row (1040B) -> conflict-free ldmatrix

// ---------------- scratch (device globals; no allocation allowed) ----------------
static __device__ __align__(16) __nv_fp8_e4m3 d_T8[4 * TROWS_ * H_]; // tables x64, fp8 (T0 incl b_fus)
static __device__ __align__(16) __half d_kh[ML_ * H_];
static __device__ __align__(16) __half d_qkAh[ML_ * H_];
static __device__ __align__(16) __half d_uh[ML_ * H_];
static __device__ __align__(16) __half d_vh[ML_ * H_];
static __device__ __align__(16) __half d_gh[ML_ * NH_ * H_];
static __device__ __align__(16) __half d_WrTh[NH_ * H_ * 64];
static __device__ __align__(16) float  d_qk[2 * NH_ * L_ * L_];
static __device__ __align__(16) __half d_attnouth[ML_ * H_];

// software grid barrier state
static __device__ unsigned int d_barcnt = 0;
static __device__ unsigned int d_bargen = 0;

__device__ __forceinline__ void grid_sync(int nb) {
    __threadfence();
    __syncthreads();
    if (threadIdx.x == 0) {
        unsigned int gen = *(volatile unsigned int*)&d_bargen;
        if (atomicAdd(&d_barcnt, 1u) == (unsigned)nb - 1u) {
            d_barcnt = 0;
            __threadfence();
            atomicAdd(&d_bargen, 1u);
        } else {
            while (*(volatile unsigned int*)&d_bargen == gen) {}
        }
        __threadfence();
    }
    __syncthreads();
}

__device__ __forceinline__ float st_conv(float v, float*)  { return v; }
__device__ __forceinline__ __half st_conv(float v, __half*) { return __float2half(v); }
__device__ __forceinline__ __nv_fp8_e4m3 st_conv(float v, __nv_fp8_e4m3*) {
    return __nv_fp8_e4m3(v * 64.f);    // x64: relu(64x)=64relu(x); undone in Phase B
}

template<class T, class U> struct is_same_t { static const bool v = false; };
template<class T> struct is_same_t<T, T>    { static const bool v = true;  };

struct SmemGemm { __half As[2][64][40]; __half Bs[2][64][40]; };           // 20480 B
struct SmemAttn {                                                          // 32768 B
    __half g_s[NH_][GP_];
    __half R[16][GP_];
    float  sc[NH_][SCP_];
    int    ksp[L_], kep[L_];
};

__device__ __forceinline__ void cp16(uint32_t saddr, const void* g, int bytes) {
    asm volatile("cp.async.cg.shared.global [%0], [%1], 16, %2;"
                 :: "r"(saddr), "l"(g), "r"(bytes));
}
__device__ __forceinline__ void cp_commit() { asm volatile("cp.async.commit_group;"); }
__device__ __forceinline__ void cp_wait0()  { asm volatile("cp.async.wait_group 0;"); }

// ---------------- tensor-core HGEMM: 64x64 tile, BK=32, mma.m16n8k16 ----------------
template<typename AT, typename BT, bool ATOMIC, typename OT>
__device__ __forceinline__ void hgemm(
    SmemGemm* st, int bxi, int byi,
    const AT* __restrict__ A, int lda,
    const BT* __restrict__ B, int ldb,
    const float* __restrict__ bias,
    OT* __restrict__ C, int ldc,
    int M, int N, int K,
    const float* __restrict__ addA = nullptr,
    __half* __restrict__ C2 = nullptr,
    const float* __restrict__ add2 = nullptr)
{
    const int tid  = threadIdx.x;
    const int lane = tid & 31, warp = tid >> 5;
    const int wm = warp >> 1, wn = warp & 1;
    const int m0 = byi * 64, n0 = bxi * 64;

    float acc[4][4];
#pragma unroll
    for (int j = 0; j < 4; ++j)
#pragma unroll
        for (int r = 0; r < 4; ++r) acc[j][r] = 0.f;

    const int rf = tid >> 3, kcf = (tid & 7) * 4;
    const int rh = tid >> 2, kch = (tid & 3) * 8;

    float4 afv0, afv1, bfv0, bfv1;

    auto fetchA = [&](int k0, int buf) {
        if constexpr (is_same_t<AT, float>::v) {
            const float* Af = reinterpret_cast<const float*>(A);
            afv0 = make_float4(0.f, 0.f, 0.f, 0.f);
            afv1 = make_float4(0.f, 0.f, 0.f, 0.f);
            if (m0 + rf < M)
                afv0 = *reinterpret_cast<const float4*>(Af + (size_t)(m0 + rf) * lda + k0 + kcf);
            if (m0 + rf + 32 < M)
                afv1 = *reinterpret_cast<const float4*>(Af + (size_t)(m0 + rf + 32) * lda + k0 + kcf);
        } else {
            const __half* Ah = reinterpret_cast<const __half*>(A);
            cp16((uint32_t)__cvta_generic_to_shared(&st->As[buf][rh][kch]),
                 Ah + (size_t)(m0 + rh) * lda + k0 + kch,
                 (m0 + rh < M) ? 16 : 0);
        }
    };
    auto fetchB = [&](int k0, int buf) {
        if constexpr (is_same_t<BT, float>::v) {
            const float* Bf = reinterpret_cast<const float*>(B);
            bfv0 = make_float4(0.f, 0.f, 0.f, 0.f);
            bfv1 = make_float4(0.f, 0.f, 0.f, 0.f);
            if (n0 + rf < N)
                bfv0 = *reinterpret_cast<const float4*>(Bf + (size_t)(n0 + rf) * ldb + k0 + kcf);
            if (n0 + rf + 32 < N)
                bfv1 = *reinterpret_cast<const float4*>(Bf + (size_t)(n0 + rf + 32) * ldb + k0 + kcf);
        } else {
            const __half* Bh = reinterpret_cast<const __half*>(B);
            cp16((uint32_t)__cvta_generic_to_shared(&st->Bs[buf][rh][kch]),
                 Bh + (size_t)(n0 + rh) * ldb + k0 + kch,
                 (n0 + rh < N) ? 16 : 0);
        }
    };
    auto packh = [](const float4& f) {
        __half2 h0 = __floats2half2_rn(f.x, f.y);
        __half2 h1 = __floats2half2_rn(f.z, f.w);
        uint2 u;
        u.x = *reinterpret_cast<unsigned*>(&h0);
        u.y = *reinterpret_cast<unsigned*>(&h1);
        return u;
    };
    auto commitA = [&](int buf) {
        if constexpr (is_same_t<AT, float>::v) {
            *reinterpret_cast<uint2*>(&st->As[buf][rf][kcf])      = packh(afv0);
            *reinterpret_cast<uint2*>(&st->As[buf][rf + 32][kcf]) = packh(afv1);
        }
    };
    auto commitB = [&](int buf) {
        if constexpr (is_same_t<BT, float>::v) {
            *reinterpret_cast<uint2*>(&st->Bs[buf][rf][kcf])      = packh(bfv0);
            *reinterpret_cast<uint2*>(&st->Bs[buf][rf + 32][kcf]) = packh(bfv1);
        }
    };

    fetchA(0, 0); fetchB(0, 0);
    cp_commit();
    commitA(0); commitB(0);
    cp_wait0();
    __syncthreads();

    const int fr = lane & 15;
    const int fc = (lane >> 4) << 3;

    int buf = 0;
    for (int k0 = 0; k0 < K; k0 += 32) {
        const bool hn = (k0 + 32 < K);
        if (hn) { fetchA(k0 + 32, buf ^ 1); fetchB(k0 + 32, buf ^ 1); cp_commit(); }

#pragma unroll
        for (int ks = 0; ks < 2; ++ks) {
            uint32_t a0, a1, a2, a3;
            {
                uint32_t addr = (uint32_t)__cvta_generic_to_shared(
                    &st->As[buf][wm * 16 + fr][ks * 16 + fc]);
                asm volatile("ldmatrix.sync.aligned.m8n8.x4.shared.b16 {%0,%1,%2,%3}, [%4];"
                             : "=r"(a0), "=r"(a1), "=r"(a2), "=r"(a3) : "r"(addr));
            }
#pragma unroll
            for (int jp = 0; jp < 2; ++jp) {
                uint32_t b0, b1, b2, b3;
                uint32_t addr = (uint32_t)__cvta_generic_to_shared(
                    &st->Bs[buf][wn * 32 + jp * 16 + fr][ks * 16 + fc]);
                asm volatile("ldmatrix.sync.aligned.m8n8.x4.shared.b16 {%0,%1,%2,%3}, [%4];"
                             : "=r"(b0), "=r"(b1), "=r"(b2), "=r"(b3) : "r"(addr));
                asm volatile("mma.sync.aligned.m16n8k16.row.col.f32.f16.f16.f32 "
                             "{%0,%1,%2,%3}, {%4,%5,%6,%7}, {%8,%9}, {%0,%1,%2,%3};"
                             : "+f"(acc[2 * jp][0]), "+f"(acc[2 * jp][1]),
                               "+f"(acc[2 * jp][2]), "+f"(acc[2 * jp][3])
                             : "r"(a0), "r"(a1), "r"(a2), "r"(a3), "r"(b0), "r"(b2));
                asm volatile("mma.sync.aligned.m16n8k16.row.col.f32.f16.f16.f32 "
                             "{%0,%1,%2,%3}, {%4,%5,%6,%7}, {%8,%9}, {%0,%1,%2,%3};"
                             : "+f"(acc[2 * jp + 1][0]), "+f"(acc[2 * jp + 1][1]),
                               "+f"(acc[2 * jp + 1][2]), "+f"(acc[2 * jp + 1][3])
                             : "r"(a0), "r"(a1), "r"(a2), "r"(a3), "r"(b1), "r"(b3));
            }
        }
        if (hn) { commitA(buf ^ 1); commitB(buf ^ 1); cp_wait0(); }
        __syncthreads();
        buf ^= 1;
    }

    const int er = lane >> 2;
    const int ec = (lane & 3) * 2;
#pragma unroll
    for (int j = 0; j < 4; ++j) {
        const int colb = n0 + wn * 32 + j * 8 + ec;
#pragma unroll
        for (int rr = 0; rr < 2; ++rr) {
            const int row = m0 + wm * 16 + er + rr * 8;
            if (row < M) {
#pragma unroll
                for (int cc = 0; cc < 2; ++cc) {
                    const int c = colb + cc;
                    if (c < N) {
                        float v = acc[j][rr * 2 + cc];
                        if (bias) v += bias[c];
                        if (ATOMIC) {
                            atomicAdd(reinterpret_cast<float*>(&C[(size_t)row * ldc + c]), v);
                        } else {
                            float v1 = v;
                            if (addA) v1 += addA[c];
                            C[(size_t)row * ldc + c] = st_conv(v1, (OT*)nullptr);
                            if (C2) C2[(size_t)row * ldc + c] = __float2half(v + add2[c]);
                        }
                    }
                }
            }
        }
    }
}

// 16 fp8 (uint4) -> 8 half2
__device__ __forceinline__ void cvt_fp8x16(const uint4& v, __half2* out) {
    const uint32_t w[4] = {v.x, v.y, v.z, v.w};
#pragma unroll
    for (int i = 0; i < 4; ++i) {
        unsigned short lo = (unsigned short)(w[i] & 0xffffu);
        unsigned short hi = (unsigned short)(w[i] >> 16);
        uint32_t r0, r1;
        asm("cvt.rn.f16x2.e4m3x2 %0, %1;" : "=r"(r0) : "h"(lo));
        asm("cvt.rn.f16x2.e4m3x2 %0, %1;" : "=r"(r1) : "h"(hi));
        out[2 * i]     = *reinterpret_cast<__half2*>(&r0);
        out[2 * i + 1] = *reinterpret_cast<__half2*>(&r1);
    }
}

// ------ attn body for one (b,q) row (identical math to R15 k_attn) ------
__device__ void attn_one(SmemAttn* s, int m,
                         const int* __restrict__ pos_s,
                         const int* __restrict__ pos_e,
                         const int* __restrict__ seq_len)
{
    const int b = m / L_;
    const int qi = m % L_;
    const int tid = threadIdx.x;
    const int lane = tid & 31;
    const int warp = tid >> 5;

    __syncthreads();   // protect smem reuse across consecutive jobs

    for (int i = tid; i < (NH_ * H_) / 8; i += 256) {
        const int n = i >> 6;
        const int c = i & 63;
        *reinterpret_cast<uint4*>(&s->g_s[n][c * 8]) =
            *reinterpret_cast<const uint4*>(d_gh + (size_t)m * (NH_ * H_) + n * H_ + c * 8);
    }
    for (int i = tid; i < NH_ * L_; i += 256) {
        const int n = i / L_, k = i % L_;
        s->sc[n][k] = d_qk[((size_t)(b * NH_ + n) * L_ + qi) * L_ + k];
    }
    for (int i = tid; i < L_; i += 256) {
        s->ksp[i] = pos_s[b * L_ + i];
        s->kep[i] = pos_e[b * L_ + i];
    }
    const int psq = pos_s[m], peq = pos_e[m];
    const int slen = seq_len[b];
    __syncthreads();

    const __half2 hz = __float2half2_rn(0.f);
    const uint8_t* __restrict__ T8 = reinterpret_cast<const uint8_t*>(d_T8);
    const int lane16 = lane << 4;
    const int fr = lane & 15;
    const int fc = (lane >> 4) << 3;
    const int er = lane >> 2;
    const int ec = (lane & 3) * 2;
    const int nch = (slen + 15) >> 4;

    uint4 A0, A1, A2, A3;
    auto loadKey = [&](int kk) {
        A0 = *reinterpret_cast<const uint4*>(T8 + (size_t)((0 * TROWS_ + psq - s->ksp[kk] + 191) << 9) + lane16);
        A1 = *reinterpret_cast<const uint4*>(T8 + (size_t)((1 * TROWS_ + psq - s->kep[kk] + 191) << 9) + lane16);
        A2 = *reinterpret_cast<const uint4*>(T8 + (size_t)((2 * TROWS_ + peq - s->ksp[kk] + 191) << 9) + lane16);
        A3 = *reinterpret_cast<const uint4*>(T8 + (size_t)((3 * TROWS_ + peq - s->kep[kk] + 191) << 9) + lane16);
    };
    auto reluStore = [&](int kl) {
        __half2 t0[8], t1[8], t2[8], t3[8];
        cvt_fp8x16(A0, t0); cvt_fp8x16(A1, t1);
        cvt_fp8x16(A2, t2); cvt_fp8x16(A3, t3);
        __half2 r[8];
#pragma unroll
        for (int j = 0; j < 8; ++j) {
            __half2 ss = __hadd2(__hadd2(t0[j], t1[j]), __hadd2(t2[j], t3[j]));
            r[j] = __hmax2(ss, hz);
        }
        *reinterpret_cast<uint4*>(&s->R[kl][lane16])     = *reinterpret_cast<uint4*>(&r[0]);
        *reinterpret_cast<uint4*>(&s->R[kl][lane16 + 8]) = *reinterpret_cast<uint4*>(&r[4]);
    };

    const int kl0 = warp * 2;
    loadKey(kl0);
#pragma unroll 1
    for (int ch = 0; ch < nch; ++ch) {
        const int kb = ch * 16;
        reluStore(kl0);
        loadKey(kb + kl0 + 1);
        reluStore(kl0 + 1);
        if (ch + 1 < nch) loadKey(kb + 16 + kl0);
        __syncthreads();

        float acc[4] = {0.f, 0.f, 0.f, 0.f};
#pragma unroll
        for (int ks = 0; ks < 4; ++ks) {
            const int kd = (warp * 4 + ks) * 16;
            uint32_t a0, a1, a2, a3;
            uint32_t addrA = (uint32_t)__cvta_generic_to_shared(&s->R[fr][kd + fc]);
            asm volatile("ldmatrix.sync.aligned.m8n8.x4.shared.b16 {%0,%1,%2,%3}, [%4];"
                         : "=r"(a0), "=r"(a1), "=r"(a2), "=r"(a3) : "r"(addrA));
            uint32_t b0, b1;
            uint32_t addrB = (uint32_t)__cvta_generic_to_shared(
                &s->g_s[lane & 7][kd + ((lane >> 3) & 1) * 8]);
            asm volatile("ldmatrix.sync.aligned.m8n8.x2.shared.b16 {%0,%1}, [%2];"
                         : "=r"(b0), "=r"(b1) : "r"(addrB));
            asm volatile("mma.sync.aligned.m16n8k16.row.col.f32.f16.f16.f32 "
                         "{%0,%1,%2,%3}, {%4,%5,%6,%7}, {%8,%9}, {%0,%1,%2,%3};"
                         : "+f"(acc[0]), "+f"(acc[1]), "+f"(acc[2]), "+f"(acc[3])
                         : "r"(a0), "r"(a1), "r"(a2), "r"(a3), "r"(b0), "r"(b1));
        }
        const float is = 1.f / 64.f;
        atomicAdd(&s->sc[ec][kb + er], acc[0] * is);
        atomicAdd(&s->sc[ec + 1][kb + er], acc[1] * is);
        atomicAdd(&s->sc[ec][kb + er + 8], acc[2] * is);
        atomicAdd(&s->sc[ec + 1][kb + er + 8], acc[3] * is);
        __syncthreads();
    }

    // softmax over k (scale + mask fused), warp = head
    {
        const int n = warp;
        float val[6];
        float mx = -3.4e38f;
#pragma unroll
        for (int j = 0; j < 6; ++j) {
            const int k = lane + 32 * j;
            const float v = s->sc[n][k] * 0.125f;
            val[j] = (k < slen) ? v : -1e30f;
            mx = fmaxf(mx, val[j]);
        }
#pragma unroll
        for (int ss = 16; ss > 0; ss >>= 1) mx = fmaxf(mx, __shfl_xor_sync(0xffffffffu, mx, ss));
        float sum = 0.f;
#pragma unroll
        for (int j = 0; j < 6; ++j) {
            val[j] = __expf(val[j] - mx);
            sum += val[j];
        }
#pragma unroll
        for (int ss = 16; ss > 0; ss >>= 1) sum += __shfl_xor_sync(0xffffffffu, sum, ss);
        const float inv = 1.f / sum;
#pragma unroll
        for (int j = 0; j < 6; ++j) s->sc[n][lane + 32 * j] = val[j] * inv;
    }
    __syncwarp();

    // out[m, h] = sum_{k<slen} attn[n,k] * v_half[b,k,h]
    {
        const __half* __restrict__ vb = d_vh + (size_t)b * L_ * H_;
        const int h = tid * 2;
        const int n = warp;
        const int kmax = (slen + 3) & ~3;
        float oa = 0.f, ob = 0.f, oc = 0.f, od = 0.f;
        float pa = 0.f, pb = 0.f, pc = 0.f, pd = 0.f;
#pragma unroll 2
        for (int k = 0; k < kmax; k += 4) {
            const float a0 = s->sc[n][k],     a1 = s->sc[n][k + 1];
            const float a2 = s->sc[n][k + 2], a3 = s->sc[n][k + 3];
            __half2 v0 = *reinterpret_cast<const __half2*>(vb + (size_t)k * H_ + h);
            __half2 v1 = *reinterpret_cast<const __half2*>(vb + (size_t)(k + 1) * H_ + h);
            __half2 v2 = *reinterpret_cast<const __half2*>(vb + (size_t)(k + 2) * H_ + h);
            __half2 v3 = *reinterpret_cast<const __half2*>(vb + (size_t)(k + 3) * H_ + h);
            float2 f0 = __half22float2(v0);
            float2 f1 = __half22float2(v1);
            float2 f2 = __half22float2(v2);
            float2 f3 = __half22float2(v3);
            oa += a0 * f0.x; pa += a0 * f0.y;
            ob += a1 * f1.x; pb += a1 * f1.y;
            oc += a2 * f2.x; pc += a2 * f2.y;
            od += a3 * f3.x; pd += a3 * f3.y;
        }
        *reinterpret_cast<__half2*>(d_attnouth + (size_t)m * H_ + h) =
            __floats2half2_rn((oa + ob) + (oc + od), (pa + pb) + (pc + pd));
    }
}

// ================= single persistent kernel: all 4 stages + 3 grid barriers =================
__global__ void __launch_bounds__(256, 2) k_all(
    const float* __restrict__ key, const float* __restrict__ query, const float* __restrict__ value,
    const float* __restrict__ Wk, const float* __restrict__ bk,
    const float* __restrict__ Wq, const float* __restrict__ bq,
    const float* __restrict__ Wv, const float* __restrict__ bv,
    const float* __restrict__ pe, const float* __restrict__ W_fus,
    const float* __restrict__ b_fus, const float* __restrict__ Wr,
    const float* __restrict__ u_bias, const float* __restrict__ v_bias,
    const int* __restrict__ pos_s, const int* __restrict__ pos_e,
    const int* __restrict__ seq_len,
    const float* __restrict__ Wff, const float* __restrict__ bff,
    float* __restrict__ out, int nb)
{
    __shared__ __align__(16) unsigned char smraw[sizeof(SmemAttn)];   // 32768 B (>= SmemGemm)
    SmemGemm* sg = reinterpret_cast<SmemGemm*>(smraw);
    SmemAttn* sa = reinterpret_cast<SmemAttn*>(smraw);
    const int bid = blockIdx.x;
    const int tid = threadIdx.x;

    // ---- stage 1: projections + fp8 tables + WrT transpose + zero out ----
    for (int job = bid; job < 384; job += nb) {
        const int z = job / 48, t = job % 48;
        const int bx = t % 8, by = t / 8;
        __syncthreads();   // smem reuse guard across jobs
        if (z == 0) {
            hgemm<float, float, false, __half>(sg, bx, by, key, H_, Wk, H_, bk, d_kh, H_, ML_, H_, H_);
        } else if (z == 1) {
            hgemm<float, float, false, __half>(sg, bx, by, query, H_, Wq, H_, bq, d_qkAh, H_, ML_, H_, H_,
                                               u_bias, d_uh, v_bias);
        } else if (z == 2) {
            hgemm<float, float, false, __half>(sg, bx, by, value, H_, Wv, H_, bv, d_vh, H_, ML_, H_, H_);
        } else if (z < 7) {
            const int tt = z - 3;
            hgemm<float, float, false, __nv_fp8_e4m3>(sg, bx, by, pe + 321 * H_, H_, W_fus + tt * 256, 2 * H_,
                                                      (tt == 0) ? b_fus : nullptr,
                                                      d_T8 + (size_t)tt * TROWS_ * H_, H_, TROWS_, H_, 256);
        } else {
            const int stride = 48 * 256;
            const int start = t * 256 + tid;
            for (int i = start; i < NH_ * H_ * 64; i += stride) {
                const int h = i >> 15;
                const int rem = i & 32767;
                const int f = rem >> 6;
                const int d = rem & 63;
                d_WrTh[i] = __float2half(Wr[(size_t)(h * 64 + d) * H_ + f]);
            }
            const float4 z4 = make_float4(0.f, 0.f, 0.f, 0.f);
            float4* o4 = reinterpret_cast<float4*>(out);
            for (int i = start; i < (ML_ * H_) / 4; i += stride) o4[i] = z4;
        }
    }
    grid_sync(nb);

    // ---- stage 2: g + qk GEMMs ----
    for (int job = bid; job < 528; job += nb) {
        __syncthreads();
        if (job < 384) {
            const int z = job / 48, t = job % 48;
            hgemm<__half, __half, false, __half>(sg, t % 8, t / 8,
                                                 d_uh + z * 64, H_, d_WrTh + (size_t)z * H_ * 64, 64,
                                                 nullptr, d_gh + z * H_, NH_ * H_, ML_, H_, 64);
        } else {
            const int j2 = job - 384;          // 0..143
            const int combo = j2 / 9, tile = j2 % 9;
            const int b = combo >> 3, n = combo & 7;
            hgemm<__half, __half, false, float>(sg, tile % 3, tile / 3,
                                                d_qkAh + (size_t)b * L_ * H_ + n * 64, H_,
                                                d_kh   + (size_t)b * L_ * H_ + n * 64, H_, nullptr,
                                                d_qk + (size_t)combo * L_ * L_, L_, L_, L_, 64);
        }
    }
    grid_sync(nb);

    // ---- stage 3: attention ----
    for (int job = bid; job < ML_; job += nb)
        attn_one(sa, job, pos_s, pos_e, seq_len);
    grid_sync(nb);

    // ---- stage 4: output projection (K-split x8, atomic) ----
    for (int job = bid; job < 384; job += nb) {
        const int c = job / 48, t = job % 48;
        __syncthreads();
        hgemm<__half, float, true, float>(sg, t % 8, t / 8,
                                          d_attnouth + c * 64, H_, Wff + c * 64, H_,
                                          (c == 0) ? bff : nullptr,
                                          out, H_, ML_, H_, 64);
    }
}

// ---------------- launch ----------------
extern "C" void kernel_launch(void* const* d_in, const int* in_sizes, int n_in,
                              void* d_out, int out_size)
{
    (void)n_in; (void)out_size;
    const float* key     = (const float*)d_in[0];
    const float* query   = (const float*)d_in[1];
    const float* value   = (const float*)d_in[2];
    const int*   seq_len = (const int*)d_in[3];
    const int ip = (in_sizes[4] == 1) ? 5 : 4;   // skip lex_num if present
    const int*   pos_s  = (const int*)d_in[ip + 0];
    const int*   pos_e  = (const int*)d_in[ip + 1];
    const float* pe     = (const float*)d_in[ip + 2];
    const float* W_fus  = (const float*)d_in[ip + 3];
    const float* b_fus  = (const float*)d_in[ip + 4];
    const float* Wk     = (const float*)d_in[ip + 5];
    const float* bk     = (const float*)d_in[ip + 6];
    const float* Wq     = (const float*)d_in[ip + 7];
    const float* bq     = (const float*)d_in[ip + 8];
    const float* Wv     = (const float*)d_in[ip + 9];
    const float* bv     = (const float*)d_in[ip + 10];
    const float* Wr     = (const float*)d_in[ip + 11];
    const float* u_bias = (const float*)d_in[ip + 13];
    const float* v_bias = (const float*)d_in[ip + 14];
    const float* Wff    = (const float*)d_in[ip + 15];
    const float* bff    = (const float*)d_in[ip + 16];
    // d_in[ip+12] (br) intentionally unused: constant over k under softmax

    int nsm = 148;
    cudaDeviceGetAttribute(&nsm, cudaDevAttrMultiProcessorCount, 0);
    const int nb = nsm * 2;    // __launch_bounds__(256,2) guarantees co-residency

    k_all<<<nb, 256>>>(key, query, value, Wk, bk, Wq, bq, Wv, bv,
                       pe, W_fus, b_fus, Wr, u_bias, v_bias,
                       pos_s, pos_e, seq_len, Wff, bff,
                       (float*)d_out, nb);
}

// round 17
// speedup vs baseline: 1.4165x; 1.4165x over previous
#include <cuda_runtime.h>
#include <cuda_fp16.h>
#include <cuda_fp8.h>
#include <cstdint>
#include <cstddef>

#define B_    2
#define L_    192
#define H_    512
#define NH_   8
#define ML_   (B_*L_)     // 384 rows (b,l) flattened
#define TROWS_ 383        // distinct position diffs: [-191, 191]
#define SCP_  196         // padded score row
#define GP_   520         // padded half row (1040B) -> conflict-free ldmatrix

// ---------------- scratch (device globals; no allocation allowed) ----------------
static __device__ __align__(16) __nv_fp8_e4m3 d_T8[4 * TROWS_ * H_]; // tables x64, fp8 (T0 incl b_fus)
static __device__ __align__(16) __half d_kh[ML_ * H_];
static __device__ __align__(16) __half d_qkAh[ML_ * H_];        // qproj + bq + u_bias (half)
static __device__ __align__(16) __half d_uh[ML_ * H_];          // qproj + bq + v_bias (half)
static __device__ __align__(16) __half d_vh[ML_ * H_];
static __device__ __align__(16) __half d_gh[ML_ * NH_ * H_];
static __device__ __align__(16) __half d_WrTh[NH_ * H_ * 64];   // Wr transposed per head [h][f][d]
static __device__ __align__(16) float  d_qk[2 * NH_ * L_ * L_];
static __device__ __align__(16) __half d_attnouth[ML_ * H_];

__device__ __forceinline__ float st_conv(float v, float*)  { return v; }
__device__ __forceinline__ __half st_conv(float v, __half*) { return __float2half(v); }
__device__ __forceinline__ __nv_fp8_e4m3 st_conv(float v, __nv_fp8_e4m3*) {
    return __nv_fp8_e4m3(v * 64.f);    // x64: relu(64x)=64relu(x); undone in Phase B
}

template<class T, class U> struct is_same_t { static const bool v = false; };
template<class T> struct is_same_t<T, T>    { static const bool v = true;  };

__device__ __forceinline__ void cp16(uint32_t saddr, const void* g, int bytes) {
    asm volatile("cp.async.cg.shared.global [%0], [%1], 16, %2;"
                 :: "r"(saddr), "l"(g), "r"(bytes));
}
__device__ __forceinline__ void cp_commit() { asm volatile("cp.async.commit_group;"); }
__device__ __forceinline__ void cp_wait0()  { asm volatile("cp.async.wait_group 0;"); }

// ---------------- tensor-core HGEMM: 64x64 tile, BK=32, mma.m16n8k16 ----------------
// half sources use cp.async straight into smem; fp32 sources stage in regs + convert.
template<typename AT, typename BT, bool ATOMIC, typename OT>
__device__ __forceinline__ void hgemm(
    int bxi, int byi,
    const AT* __restrict__ A, int lda,
    const BT* __restrict__ B, int ldb,
    const float* __restrict__ bias,
    OT* __restrict__ C, int ldc,
    int M, int N, int K,
    const float* __restrict__ addA = nullptr,
    __half* __restrict__ C2 = nullptr,
    const float* __restrict__ add2 = nullptr)
{
    __shared__ __half As[2][64][40];
    __shared__ __half Bs[2][64][40];
    const int tid  = threadIdx.x;
    const int lane = tid & 31, warp = tid >> 5;
    const int wm = warp >> 1, wn = warp & 1;
    const int m0 = byi * 64, n0 = bxi * 64;

    float acc[4][4];
#pragma unroll
    for (int j = 0; j < 4; ++j)
#pragma unroll
        for (int r = 0; r < 4; ++r) acc[j][r] = 0.f;

    const int rf = tid >> 3, kcf = (tid & 7) * 4;
    const int rh = tid >> 2, kch = (tid & 3) * 8;

    float4 afv0, afv1, bfv0, bfv1;

    auto fetchA = [&](int k0, int buf) {
        if constexpr (is_same_t<AT, float>::v) {
            const float* Af = reinterpret_cast<const float*>(A);
            afv0 = make_float4(0.f, 0.f, 0.f, 0.f);
            afv1 = make_float4(0.f, 0.f, 0.f, 0.f);
            if (m0 + rf < M)
                afv0 = *reinterpret_cast<const float4*>(Af + (size_t)(m0 + rf) * lda + k0 + kcf);
            if (m0 + rf + 32 < M)
                afv1 = *reinterpret_cast<const float4*>(Af + (size_t)(m0 + rf + 32) * lda + k0 + kcf);
        } else {
            const __half* Ah = reinterpret_cast<const __half*>(A);
            cp16((uint32_t)__cvta_generic_to_shared(&As[buf][rh][kch]),
                 Ah + (size_t)(m0 + rh) * lda + k0 + kch,
                 (m0 + rh < M) ? 16 : 0);
        }
    };
    auto fetchB = [&](int k0, int buf) {
        if constexpr (is_same_t<BT, float>::v) {
            const float* Bf = reinterpret_cast<const float*>(B);
            bfv0 = make_float4(0.f, 0.f, 0.f, 0.f);
            bfv1 = make_float4(0.f, 0.f, 0.f, 0.f);
            if (n0 + rf < N)
                bfv0 = *reinterpret_cast<const float4*>(Bf + (size_t)(n0 + rf) * ldb + k0 + kcf);
            if (n0 + rf + 32 < N)
                bfv1 = *reinterpret_cast<const float4*>(Bf + (size_t)(n0 + rf + 32) * ldb + k0 + kcf);
        } else {
            const __half* Bh = reinterpret_cast<const __half*>(B);
            cp16((uint32_t)__cvta_generic_to_shared(&Bs[buf][rh][kch]),
                 Bh + (size_t)(n0 + rh) * ldb + k0 + kch,
                 (n0 + rh < N) ? 16 : 0);
        }
    };
    auto packh = [](const float4& f) {
        __half2 h0 = __floats2half2_rn(f.x, f.y);
        __half2 h1 = __floats2half2_rn(f.z, f.w);
        uint2 u;
        u.x = *reinterpret_cast<unsigned*>(&h0);
        u.y = *reinterpret_cast<unsigned*>(&h1);
        return u;
    };
    auto commitA = [&](int buf) {
        if constexpr (is_same_t<AT, float>::v) {
            *reinterpret_cast<uint2*>(&As[buf][rf][kcf])      = packh(afv0);
            *reinterpret_cast<uint2*>(&As[buf][rf + 32][kcf]) = packh(afv1);
        }
    };
    auto commitB = [&](int buf) {
        if constexpr (is_same_t<BT, float>::v) {
            *reinterpret_cast<uint2*>(&Bs[buf][rf][kcf])      = packh(bfv0);
            *reinterpret_cast<uint2*>(&Bs[buf][rf + 32][kcf]) = packh(bfv1);
        }
    };

    fetchA(0, 0); fetchB(0, 0);
    cp_commit();
    commitA(0); commitB(0);
    cp_wait0();
    __syncthreads();

    const int fr = lane & 15;
    const int fc = (lane >> 4) << 3;

    int buf = 0;
    for (int k0 = 0; k0 < K; k0 += 32) {
        const bool hn = (k0 + 32 < K);
        if (hn) { fetchA(k0 + 32, buf ^ 1); fetchB(k0 + 32, buf ^ 1); cp_commit(); }

#pragma unroll
        for (int ks = 0; ks < 2; ++ks) {
            uint32_t a0, a1, a2, a3;
            {
                uint32_t addr = (uint32_t)__cvta_generic_to_shared(
                    &As[buf][wm * 16 + fr][ks * 16 + fc]);
                asm volatile("ldmatrix.sync.aligned.m8n8.x4.shared.b16 {%0,%1,%2,%3}, [%4];"
                             : "=r"(a0), "=r"(a1), "=r"(a2), "=r"(a3) : "r"(addr));
            }
#pragma unroll
            for (int jp = 0; jp < 2; ++jp) {
                uint32_t b0, b1, b2, b3;
                uint32_t addr = (uint32_t)__cvta_generic_to_shared(
                    &Bs[buf][wn * 32 + jp * 16 + fr][ks * 16 + fc]);
                asm volatile("ldmatrix.sync.aligned.m8n8.x4.shared.b16 {%0,%1,%2,%3}, [%4];"
                             : "=r"(b0), "=r"(b1), "=r"(b2), "=r"(b3) : "r"(addr));
                asm volatile("mma.sync.aligned.m16n8k16.row.col.f32.f16.f16.f32 "
                             "{%0,%1,%2,%3}, {%4,%5,%6,%7}, {%8,%9}, {%0,%1,%2,%3};"
                             : "+f"(acc[2 * jp][0]), "+f"(acc[2 * jp][1]),
                               "+f"(acc[2 * jp][2]), "+f"(acc[2 * jp][3])
                             : "r"(a0), "r"(a1), "r"(a2), "r"(a3), "r"(b0), "r"(b2));
                asm volatile("mma.sync.aligned.m16n8k16.row.col.f32.f16.f16.f32 "
                             "{%0,%1,%2,%3}, {%4,%5,%6,%7}, {%8,%9}, {%0,%1,%2,%3};"
                             : "+f"(acc[2 * jp + 1][0]), "+f"(acc[2 * jp + 1][1]),
                               "+f"(acc[2 * jp + 1][2]), "+f"(acc[2 * jp + 1][3])
                             : "r"(a0), "r"(a1), "r"(a2), "r"(a3), "r"(b1), "r"(b3));
            }
        }
        if (hn) { commitA(buf ^ 1); commitB(buf ^ 1); cp_wait0(); }
        __syncthreads();
        buf ^= 1;
    }

    const int er = lane >> 2;
    const int ec = (lane & 3) * 2;
#pragma unroll
    for (int j = 0; j < 4; ++j) {
        const int colb = n0 + wn * 32 + j * 8 + ec;
#pragma unroll
        for (int rr = 0; rr < 2; ++rr) {
            const int row = m0 + wm * 16 + er + rr * 8;
            if (row < M) {
#pragma unroll
                for (int cc = 0; cc < 2; ++cc) {
                    const int c = colb + cc;
                    if (c < N) {
                        float v = acc[j][rr * 2 + cc];
                        if (bias) v += bias[c];
                        if (ATOMIC) {
                            atomicAdd(reinterpret_cast<float*>(&C[(size_t)row * ldc + c]), v);
                        } else {
                            float v1 = v;
                            if (addA) v1 += addA[c];
                            C[(size_t)row * ldc + c] = st_conv(v1, (OT*)nullptr);
                            if (C2) C2[(size_t)row * ldc + c] = __float2half(v + add2[c]);
                        }
                    }
                }
            }
        }
    }
}

// ---------------- stage 1: projections + pe tables (fp8 x64) + Wr transpose + zero out ----------------
__global__ void __launch_bounds__(256) k_pre(
    const float* __restrict__ key, const float* __restrict__ query, const float* __restrict__ value,
    const float* __restrict__ Wk, const float* __restrict__ bk,
    const float* __restrict__ Wq, const float* __restrict__ bq,
    const float* __restrict__ Wv, const float* __restrict__ bv,
    const float* __restrict__ pe, const float* __restrict__ W_fus,
    const float* __restrict__ b_fus, const float* __restrict__ Wr,
    const float* __restrict__ u_bias, const float* __restrict__ v_bias,
    float* __restrict__ out)
{
    const int z = blockIdx.z;
    const int bx = blockIdx.x, by = blockIdx.y;
    if (z == 0) {
        hgemm<float, float, false, __half>(bx, by, key, H_, Wk, H_, bk, d_kh, H_, ML_, H_, H_);
    } else if (z == 1) {
        hgemm<float, float, false, __half>(bx, by, query, H_, Wq, H_, bq, d_qkAh, H_, ML_, H_, H_,
                                           u_bias, d_uh, v_bias);
    } else if (z == 2) {
        hgemm<float, float, false, __half>(bx, by, value, H_, Wv, H_, bv, d_vh, H_, ML_, H_, H_);
    } else if (z < 7) {
        const int t = z - 3;   // tables 0..3; b_fus folded into T0; stored fp8 x64
        hgemm<float, float, false, __nv_fp8_e4m3>(bx, by, pe + 321 * H_, H_, W_fus + t * 256, 2 * H_,
                                                  (t == 0) ? b_fus : nullptr,
                                                  d_T8 + (size_t)t * TROWS_ * H_, H_, TROWS_, H_, 256);
    } else {
        const int stride = 48 * 256;
        const int start = (by * 8 + bx) * 256 + threadIdx.x;
        for (int i = start; i < NH_ * H_ * 64; i += stride) {
            const int h = i >> 15;
            const int rem = i & 32767;
            const int f = rem >> 6;
            const int d = rem & 63;
            d_WrTh[i] = __float2half(Wr[(size_t)(h * 64 + d) * H_ + f]);
        }
        const float4 z4 = make_float4(0.f, 0.f, 0.f, 0.f);
        float4* o4 = reinterpret_cast<float4*>(out);
        for (int i = start; i < (ML_ * H_) / 4; i += stride) o4[i] = z4;
    }
}

// -------- stage 2: g + per-head qk GEMMs (compact grid), PDL-dependent --------
__global__ void __launch_bounds__(256) k_gqk()
{
#if __CUDA_ARCH__ >= 900
    cudaGridDependencySynchronize();
#endif
    const int z = blockIdx.z;
    if (z < 8) {
        hgemm<__half, __half, false, __half>(blockIdx.x, blockIdx.y,
                                             d_uh + z * 64, H_, d_WrTh + (size_t)z * H_ * 64, 64,
                                             nullptr, d_gh + z * H_, NH_ * H_, ML_, H_, 64);
    } else {
        const int t = (z - 8) * 48 + blockIdx.y * 8 + blockIdx.x;
        if (t >= 144) return;
        const int combo = t / 9, tile = t % 9;
        const int b = combo >> 3, n = combo & 7;
        hgemm<__half, __half, false, float>(tile % 3, tile / 3,
                                            d_qkAh + (size_t)b * L_ * H_ + n * 64, H_,
                                            d_kh   + (size_t)b * L_ * H_ + n * 64, H_, nullptr,
                                            d_qk + (size_t)combo * L_ * L_, L_, L_, L_, 64);
    }
}

// 16 fp8 (uint4) -> 8 half2
__device__ __forceinline__ void cvt_fp8x16(const uint4& v, __half2* out) {
    const uint32_t w[4] = {v.x, v.y, v.z, v.w};
#pragma unroll
    for (int i = 0; i < 4; ++i) {
        unsigned short lo = (unsigned short)(w[i] & 0xffffu);
        unsigned short hi = (unsigned short)(w[i] >> 16);
        uint32_t r0, r1;
        asm("cvt.rn.f16x2.e4m3x2 %0, %1;" : "=r"(r0) : "h"(lo));
        asm("cvt.rn.f16x2.e4m3x2 %0, %1;" : "=r"(r1) : "h"(hi));
        out[2 * i]     = *reinterpret_cast<__half2*>(&r0);
        out[2 * i + 1] = *reinterpret_cast<__half2*>(&r1);
    }
}

// ------ stage 3: fused rel-scores (tensor-core, fp8 tables) + softmax + attn@V ------
__global__ void __launch_bounds__(256, 3) k_attn(
    const int* __restrict__ pos_s,
    const int* __restrict__ pos_e,
    const int* __restrict__ seq_len)
{
    __shared__ __align__(16) __half g_s[NH_][GP_];
    __shared__ __align__(16) __half R[16][GP_];
    __shared__ __align__(16) float sc[NH_][SCP_];
    __shared__ int ksp[L_], kep[L_];

    const int m = blockIdx.x;          // b*L + q
    const int b = m / L_;
    const int qi = m % L_;
    const int tid = threadIdx.x;
    const int lane = tid & 31;
    const int warp = tid >> 5;

    // independent inputs may load before the dependency sync
    for (int i = tid; i < L_; i += 256) { ksp[i] = pos_s[b * L_ + i]; kep[i] = pos_e[b * L_ + i]; }
    const int psq = pos_s[m], peq = pos_e[m];
    const int slen = seq_len[b];

#if __CUDA_ARCH__ >= 900
    cudaGridDependencySynchronize();
#endif

    for (int i = tid; i < (NH_ * H_) / 8; i += 256) {
        const int n = i >> 6;
        const int c = i & 63;
        *reinterpret_cast<uint4*>(&g_s[n][c * 8]) =
            *reinterpret_cast<const uint4*>(d_gh + (size_t)m * (NH_ * H_) + n * H_ + c * 8);
    }
    for (int i = tid; i < NH_ * L_; i += 256) {
        const int n = i / L_, k = i % L_;
        sc[n][k] = d_qk[((size_t)(b * NH_ + n) * L_ + qi) * L_ + k];
    }
    __syncthreads();

    const __half2 hz = __float2half2_rn(0.f);
    const uint8_t* __restrict__ T8 = reinterpret_cast<const uint8_t*>(d_T8);
    const int lane16 = lane << 4;
    const int fr = lane & 15;
    const int fc = (lane >> 4) << 3;
    const int er = lane >> 2;
    const int ec = (lane & 3) * 2;
    const int nch = (slen + 15) >> 4;

    uint4 A0, A1, A2, A3;
    auto loadKey = [&](int kk) {
        A0 = *reinterpret_cast<const uint4*>(T8 + (size_t)((0 * TROWS_ + psq - ksp[kk] + 191) << 9) + lane16);
        A1 = *reinterpret_cast<const uint4*>(T8 + (size_t)((1 * TROWS_ + psq - kep[kk] + 191) << 9) + lane16);
        A2 = *reinterpret_cast<const uint4*>(T8 + (size_t)((2 * TROWS_ + peq - ksp[kk] + 191) << 9) + lane16);
        A3 = *reinterpret_cast<const uint4*>(T8 + (size_t)((3 * TROWS_ + peq - kep[kk] + 191) << 9) + lane16);
    };
    auto reluStore = [&](int kl) {
        __half2 t0[8], t1[8], t2[8], t3[8];
        cvt_fp8x16(A0, t0); cvt_fp8x16(A1, t1);
        cvt_fp8x16(A2, t2); cvt_fp8x16(A3, t3);
        __half2 r[8];
#pragma unroll
        for (int j = 0; j < 8; ++j) {
            __half2 s = __hadd2(__hadd2(t0[j], t1[j]), __hadd2(t2[j], t3[j]));
            r[j] = __hmax2(s, hz);
        }
        *reinterpret_cast<uint4*>(&R[kl][lane16])     = *reinterpret_cast<uint4*>(&r[0]);
        *reinterpret_cast<uint4*>(&R[kl][lane16 + 8]) = *reinterpret_cast<uint4*>(&r[4]);
    };

    const int kl0 = warp * 2;
    loadKey(kl0);
#pragma unroll 1
    for (int ch = 0; ch < nch; ++ch) {
        const int kb = ch * 16;
        reluStore(kl0);
        loadKey(kb + kl0 + 1);
        reluStore(kl0 + 1);
        if (ch + 1 < nch) loadKey(kb + 16 + kl0);
        __syncthreads();

        float acc[4] = {0.f, 0.f, 0.f, 0.f};
#pragma unroll
        for (int ks = 0; ks < 4; ++ks) {
            const int kd = (warp * 4 + ks) * 16;
            uint32_t a0, a1, a2, a3;
            uint32_t addrA = (uint32_t)__cvta_generic_to_shared(&R[fr][kd + fc]);
            asm volatile("ldmatrix.sync.aligned.m8n8.x4.shared.b16 {%0,%1,%2,%3}, [%4];"
                         : "=r"(a0), "=r"(a1), "=r"(a2), "=r"(a3) : "r"(addrA));
            uint32_t b0, b1;
            uint32_t addrB = (uint32_t)__cvta_generic_to_shared(
                &g_s[lane & 7][kd + ((lane >> 3) & 1) * 8]);
            asm volatile("ldmatrix.sync.aligned.m8n8.x2.shared.b16 {%0,%1}, [%2];"
                         : "=r"(b0), "=r"(b1) : "r"(addrB));
            asm volatile("mma.sync.aligned.m16n8k16.row.col.f32.f16.f16.f32 "
                         "{%0,%1,%2,%3}, {%4,%5,%6,%7}, {%8,%9}, {%0,%1,%2,%3};"
                         : "+f"(acc[0]), "+f"(acc[1]), "+f"(acc[2]), "+f"(acc[3])
                         : "r"(a0), "r"(a1), "r"(a2), "r"(a3), "r"(b0), "r"(b1));
        }
        const float is = 1.f / 64.f;
        atomicAdd(&sc[ec][kb + er], acc[0] * is);
        atomicAdd(&sc[ec + 1][kb + er], acc[1] * is);
        atomicAdd(&sc[ec][kb + er + 8], acc[2] * is);
        atomicAdd(&sc[ec + 1][kb + er + 8], acc[3] * is);
        __syncthreads();
    }

    // softmax over k (scale + mask fused), warp = head
    {
        const int n = warp;
        float val[6];
        float mx = -3.4e38f;
#pragma unroll
        for (int j = 0; j < 6; ++j) {
            const int k = lane + 32 * j;
            const float v = sc[n][k] * 0.125f;
            val[j] = (k < slen) ? v : -1e30f;
            mx = fmaxf(mx, val[j]);
        }
#pragma unroll
        for (int s = 16; s > 0; s >>= 1) mx = fmaxf(mx, __shfl_xor_sync(0xffffffffu, mx, s));
        float sum = 0.f;
#pragma unroll
        for (int j = 0; j < 6; ++j) {
            val[j] = __expf(val[j] - mx);
            sum += val[j];
        }
#pragma unroll
        for (int s = 16; s > 0; s >>= 1) sum += __shfl_xor_sync(0xffffffffu, sum, s);
        const float inv = 1.f / sum;
#pragma unroll
        for (int j = 0; j < 6; ++j) sc[n][lane + 32 * j] = val[j] * inv;
    }
    __syncwarp();

    // out[m, h] = sum_{k<slen} attn[n,k] * v_half[b,k,h]
    {
        const __half* __restrict__ vb = d_vh + (size_t)b * L_ * H_;
        const int h = tid * 2;
        const int n = warp;
        const int kmax = (slen + 3) & ~3;
        float oa = 0.f, ob = 0.f, oc = 0.f, od = 0.f;
        float pa = 0.f, pb = 0.f, pc = 0.f, pd = 0.f;
#pragma unroll 2
        for (int k = 0; k < kmax; k += 4) {
            const float a0 = sc[n][k],     a1 = sc[n][k + 1];
            const float a2 = sc[n][k + 2], a3 = sc[n][k + 3];
            __half2 v0 = *reinterpret_cast<const __half2*>(vb + (size_t)k * H_ + h);
            __half2 v1 = *reinterpret_cast<const __half2*>(vb + (size_t)(k + 1) * H_ + h);
            __half2 v2 = *reinterpret_cast<const __half2*>(vb + (size_t)(k + 2) * H_ + h);
            __half2 v3 = *reinterpret_cast<const __half2*>(vb + (size_t)(k + 3) * H_ + h);
            float2 f0 = __half22float2(v0);
            float2 f1 = __half22float2(v1);
            float2 f2 = __half22float2(v2);
            float2 f3 = __half22float2(v3);
            oa += a0 * f0.x; pa += a0 * f0.y;
            ob += a1 * f1.x; pb += a1 * f1.y;
            oc += a2 * f2.x; pc += a2 * f2.y;
            od += a3 * f3.x; pd += a3 * f3.y;
        }
        *reinterpret_cast<__half2*>(d_attnouth + (size_t)m * H_ + h) =
            __floats2half2_rn((oa + ob) + (oc + od), (pa + pb) + (pc + pd));
    }
}

// ---------------- stage 4: output projection, K-split x8 + atomic epilogue ----------------
__global__ void __launch_bounds__(256) k_ff(const float* __restrict__ Wff,
                                            const float* __restrict__ bff,
                                            float* __restrict__ out)
{
#if __CUDA_ARCH__ >= 900
    cudaGridDependencySynchronize();
#endif
    const int c = blockIdx.z;
    hgemm<__half, float, true, float>(blockIdx.x, blockIdx.y,
                                      d_attnouth + c * 64, H_, Wff + c * 64, H_,
                                      (c == 0) ? bff : nullptr,
                                      out, H_, ML_, H_, 64);
}

// ---------------- launch (PDL on dependent kernels) ----------------
template<typename F, typename... Args>
static void launch_pdl(dim3 grid, F func, Args... args)
{
    cudaLaunchConfig_t cfg = {};
    cfg.gridDim = grid;
    cfg.blockDim = dim3(256, 1, 1);
    cudaLaunchAttribute attr[1];
    attr[0].id = cudaLaunchAttributeProgrammaticStreamSerialization;
    attr[0].val.programmaticStreamSerializationAllowed = 1;
    cfg.attrs = attr;
    cfg.numAttrs = 1;
    cudaLaunchKernelEx(&cfg, func, args...);
}

extern "C" void kernel_launch(void* const* d_in, const int* in_sizes, int n_in,
                              void* d_out, int out_size)
{
    (void)n_in; (void)out_size;
    const float* key     = (const float*)d_in[0];
    const float* query   = (const float*)d_in[1];
    const float* value   = (const float*)d_in[2];
    const int*   seq_len = (const int*)d_in[3];
    const int ip = (in_sizes[4] == 1) ? 5 : 4;   // skip lex_num if present
    const int*   pos_s  = (const int*)d_in[ip + 0];
    const int*   pos_e  = (const int*)d_in[ip + 1];
    const float* pe     = (const float*)d_in[ip + 2];
    const float* W_fus  = (const float*)d_in[ip + 3];
    const float* b_fus  = (const float*)d_in[ip + 4];
    const float* Wk     = (const float*)d_in[ip + 5];
    const float* bk     = (const float*)d_in[ip + 6];
    const float* Wq     = (const float*)d_in[ip + 7];
    const float* bq     = (const float*)d_in[ip + 8];
    const float* Wv     = (const float*)d_in[ip + 9];
    const float* bv     = (const float*)d_in[ip + 10];
    const float* Wr     = (const float*)d_in[ip + 11];
    const float* u_bias = (const float*)d_in[ip + 13];
    const float* v_bias = (const float*)d_in[ip + 14];
    const float* Wff    = (const float*)d_in[ip + 15];
    const float* bff    = (const float*)d_in[ip + 16];
    // d_in[ip+12] (br) intentionally unused: constant over k under softmax

    k_pre<<<dim3(8, 6, 8), 256>>>(key, query, value, Wk, bk, Wq, bq, Wv, bv,
                                  pe, W_fus, b_fus, Wr, u_bias, v_bias, (float*)d_out);
    launch_pdl(dim3(8, 6, 11), k_gqk);
    launch_pdl(dim3(ML_, 1, 1), k_attn, pos_s, pos_e, seq_len);
    launch_pdl(dim3(8, 6, 8), k_ff, Wff, bff, (float*)d_out);
}